// round 2
// baseline (speedup 1.0000x reference)
#include <cuda_runtime.h>
#include <math.h>

#define TT 8
#define NNODE 10000
#define FIN 128
#define HH 128
#define HIDNN 1024
#define HID2 256
#define CC 16
#define EE 320000
#define G4 (4*HH)

// ---------------- scratch (device globals; no runtime allocation) ----------------
__device__ float g_xw[TT*NNODE*HH];
__device__ float g_h1[TT*NNODE*HH];
__device__ float g_tf[TT*NNODE*HH];
__device__ int   g_deg[TT*NNODE];
__device__ int   g_fill[TT*NNODE];
__device__ float g_dinv[TT*NNODE];
__device__ int   g_rowptr[TT*(NNODE+1)];
__device__ int   g_colsrc[TT*EE];
__device__ float g_Wt[2*TT*HH*HH];
__device__ float g_y0[NNODE*HIDNN];
__device__ float g_y1[NNODE*HID2];
__device__ float g_x2[NNODE*HH];
__device__ float g_gall[TT*NNODE*G4];
__device__ float g_ghh[NNODE*G4];
__device__ float g_hst[NNODE*HH];
__device__ float g_cst[NNODE*HH];

// ---------------- f32x2 packed-FMA helpers ----------------
__device__ __forceinline__ unsigned long long pk2(float lo, float hi){
    unsigned long long r;
    asm("mov.b64 %0, {%1, %2};" : "=l"(r) : "f"(lo), "f"(hi));
    return r;
}
__device__ __forceinline__ void ffma2(unsigned long long &d, unsigned long long a, unsigned long long b){
    asm("fma.rn.f32x2 %0, %1, %2, %0;" : "+l"(d) : "l"(a), "l"(b));
}
__device__ __forceinline__ float2 upk2(unsigned long long v){
    float2 r;
    asm("mov.b64 {%0, %1}, %2;" : "=f"(r.x), "=f"(r.y) : "l"(v));
    return r;
}

// ---------------- NT GEMM: C[M,Nc] = A[M,K] * B[Nc,K]^T (+bias, relu), batched over z ----------------
// requires K % 16 == 0, Nc % 64 == 0 (true for all call sites)
__global__ void gemm_nt_kernel(const float* __restrict__ A, const float* __restrict__ B,
                               float* __restrict__ C, int M, int K, int Nc,
                               const float* __restrict__ bias, int relu,
                               long sA, long sB, long sC)
{
    __shared__ float As[16][68];
    __shared__ float Bs[16][68];
    int z = blockIdx.z;
    A += (long)z * sA; B += (long)z * sB; C += (long)z * sC;
    int tid = threadIdx.x;
    int m0 = blockIdx.x * 64, n0 = blockIdx.y * 64;
    int lr = tid >> 2;           // 0..63
    int lk = (tid & 3) << 2;     // 0,4,8,12
    const float* Ap = A + (long)(m0 + lr) * K + lk;
    const float* Bp = B + (long)(n0 + lr) * K + lk;
    bool aval = (m0 + lr) < M;
    int ty = tid >> 4, tx = tid & 15;
    unsigned long long acc[4][2];
#pragma unroll
    for (int i = 0; i < 4; i++){ acc[i][0] = 0ULL; acc[i][1] = 0ULL; }

    for (int k0 = 0; k0 < K; k0 += 16){
        float4 av = aval ? *(const float4*)Ap : make_float4(0.f,0.f,0.f,0.f);
        float4 bv = *(const float4*)Bp;
        Ap += 16; Bp += 16;
        __syncthreads();
        As[lk+0][lr]=av.x; As[lk+1][lr]=av.y; As[lk+2][lr]=av.z; As[lk+3][lr]=av.w;
        Bs[lk+0][lr]=bv.x; Bs[lk+1][lr]=bv.y; Bs[lk+2][lr]=bv.z; Bs[lk+3][lr]=bv.w;
        __syncthreads();
#pragma unroll
        for (int kk = 0; kk < 16; kk++){
            float4 a4 = *(const float4*)&As[kk][ty*4];
            float4 b4 = *(const float4*)&Bs[kk][tx*4];
            unsigned long long b01 = pk2(b4.x, b4.y), b23 = pk2(b4.z, b4.w);
            unsigned long long a0 = pk2(a4.x, a4.x);
            unsigned long long a1 = pk2(a4.y, a4.y);
            unsigned long long a2 = pk2(a4.z, a4.z);
            unsigned long long a3 = pk2(a4.w, a4.w);
            ffma2(acc[0][0], a0, b01); ffma2(acc[0][1], a0, b23);
            ffma2(acc[1][0], a1, b01); ffma2(acc[1][1], a1, b23);
            ffma2(acc[2][0], a2, b01); ffma2(acc[2][1], a2, b23);
            ffma2(acc[3][0], a3, b01); ffma2(acc[3][1], a3, b23);
        }
    }
#pragma unroll
    for (int i = 0; i < 4; i++){
        int row = m0 + ty*4 + i;
        if (row >= M) continue;
        float2 v0 = upk2(acc[i][0]), v1 = upk2(acc[i][1]);
        int col = n0 + tx*4;
        float4 r = make_float4(v0.x, v0.y, v1.x, v1.y);
        if (bias){ r.x += bias[col]; r.y += bias[col+1]; r.z += bias[col+2]; r.w += bias[col+3]; }
        if (relu){ r.x=fmaxf(r.x,0.f); r.y=fmaxf(r.y,0.f); r.z=fmaxf(r.z,0.f); r.w=fmaxf(r.w,0.f); }
        *(float4*)(C + (long)row * Nc + col) = r;
    }
}

// ---------------- GCN prep kernels ----------------
__global__ void zero_deg_kernel(){
    int i = blockIdx.x * blockDim.x + threadIdx.x;
    if (i < TT*NNODE) g_deg[i] = 0;
}

__global__ void deg_kernel(const int* __restrict__ ei){
    int idx = blockIdx.x * blockDim.x + threadIdx.x;
    if (idx >= TT*EE) return;
    int t = idx / EE, e = idx - t*EE;
    int d = ei[t*2*EE + EE + e];
    atomicAdd(&g_deg[t*NNODE + d], 1);
}

__global__ void dinv_fill_kernel(){
    int i = blockIdx.x * blockDim.x + threadIdx.x;
    if (i >= TT*NNODE) return;
    g_dinv[i] = rsqrtf((float)(g_deg[i] + 1));   // +1 self loop
    g_fill[i] = 0;
}

__global__ void scan_rowptr_kernel(){
    int t = blockIdx.x;
    const int* d = g_deg + t*NNODE;
    int* rp = g_rowptr + t*(NNODE+1);
    __shared__ int s[1024];
    int carry = 0;
    if (threadIdx.x == 0) rp[0] = 0;
    for (int base = 0; base < NNODE; base += 1024){
        int i = base + threadIdx.x;
        int v = (i < NNODE) ? d[i] : 0;
        s[threadIdx.x] = v;
        __syncthreads();
        for (int off = 1; off < 1024; off <<= 1){
            int add = (threadIdx.x >= off) ? s[threadIdx.x - off] : 0;
            __syncthreads();
            s[threadIdx.x] += add;
            __syncthreads();
        }
        if (i < NNODE) rp[i+1] = carry + s[threadIdx.x];
        carry += s[1023];
        __syncthreads();
    }
}

__global__ void scatter_kernel(const int* __restrict__ ei){
    int idx = blockIdx.x * blockDim.x + threadIdx.x;
    if (idx >= TT*EE) return;
    int t = idx / EE, e = idx - t*EE;
    int s = ei[t*2*EE + e];
    int d = ei[t*2*EE + EE + e];
    int pos = g_rowptr[t*(NNODE+1) + d] + atomicAdd(&g_fill[t*NNODE + d], 1);
    g_colsrc[t*EE + pos] = s;
}

// sort each CSR row so float accumulation order is deterministic across replays
__global__ void sort_rows_kernel(){
    int t = blockIdx.z;
    int node = blockIdx.x * 8 + (threadIdx.x >> 5);
    int lane = threadIdx.x & 31;
    __shared__ int sh[8][256];
    if (node >= NNODE) return;
    int* buf = sh[threadIdx.x >> 5];
    int* cs = g_colsrc + t*EE;
    int s0 = g_rowptr[t*(NNODE+1) + node];
    int s1 = g_rowptr[t*(NNODE+1) + node + 1];
    int len = s1 - s0;
    if (len <= 1 || len > 256) return;
    for (int i = lane; i < len; i += 32) buf[i] = cs[s0 + i];
    __syncwarp();
    for (int p = 0; p < len; p++){
        int start = p & 1;
        for (int i = start + 2*lane; i < len - 1; i += 64){
            int a = buf[i], b = buf[i+1];
            if (a > b){ buf[i] = b; buf[i+1] = a; }
        }
        __syncwarp();
    }
    for (int i = lane; i < len; i += 32) cs[s0 + i] = buf[i];
}

__global__ void transpose_w_kernel(const float* __restrict__ W0, const float* __restrict__ W1){
    int m = blockIdx.x;  // 0..15
    const float* src = (m < TT) ? (W0 + m*HH*HH) : (W1 + (m-TT)*HH*HH);
    float* dst = g_Wt + m*HH*HH;
    for (int i = threadIdx.x; i < HH*HH; i += blockDim.x){
        int k = i >> 7, j = i & 127;
        dst[j*HH + k] = src[i];
    }
}

// ---------------- GCN aggregation: out[d] = sum_{s in row d} xw[s]*dinv[s]*dinv[d] + self ----------------
__global__ void gcn_gather_kernel(const float* __restrict__ xw, float* __restrict__ out, int relu){
    int t = blockIdx.z;
    int node = blockIdx.x * 8 + (threadIdx.x >> 5);
    if (node >= NNODE) return;
    int lane = threadIdx.x & 31;
    const float* xwT = xw + (long)t*NNODE*HH;
    float* outT = out + (long)t*NNODE*HH;
    const int* rp = g_rowptr + t*(NNODE+1);
    const int* cs = g_colsrc + t*EE;
    const float* dv = g_dinv + t*NNODE;
    float dn = dv[node];
    float4 acc = ((const float4*)(xwT + node*HH))[lane];
    float w0 = dn * dn;
    acc.x *= w0; acc.y *= w0; acc.z *= w0; acc.w *= w0;
    int e0 = rp[node], e1 = rp[node+1];
    for (int e = e0; e < e1; e++){
        int s = cs[e];
        float w = dv[s] * dn;
        float4 v = ((const float4*)(xwT + s*HH))[lane];
        acc.x += v.x * w; acc.y += v.y * w; acc.z += v.z * w; acc.w += v.w * w;
    }
    if (relu){
        acc.x = fmaxf(acc.x, 0.f); acc.y = fmaxf(acc.y, 0.f);
        acc.z = fmaxf(acc.z, 0.f); acc.w = fmaxf(acc.w, 0.f);
    }
    ((float4*)(outT + node*HH))[lane] = acc;
}

// ---------------- LSTM gate kernel (torch order i,f,g,o) ----------------
__device__ __forceinline__ float sigm(float x){ return 1.f / (1.f + expf(-x)); }

__global__ void lstm_gate_kernel(const float* __restrict__ gxt, const float* __restrict__ ghh,
                                 const float* __restrict__ bih, const float* __restrict__ bhh,
                                 float* __restrict__ h, float* __restrict__ c)
{
    int idx = blockIdx.x * blockDim.x + threadIdx.x;
    if (idx >= NNODE*HH) return;
    int n = idx >> 7, k = idx & 127;
    const float* gx = gxt + n*G4;
    const float* gh = ghh + n*G4;
    float gi = gx[k]       + gh[k]       + bih[k]       + bhh[k];
    float gf = gx[HH+k]    + gh[HH+k]    + bih[HH+k]    + bhh[HH+k];
    float gg = gx[2*HH+k]  + gh[2*HH+k]  + bih[2*HH+k]  + bhh[2*HH+k];
    float go = gx[3*HH+k]  + gh[3*HH+k]  + bih[3*HH+k]  + bhh[3*HH+k];
    float cn = sigm(gf) * c[idx] + sigm(gi) * tanhf(gg);
    c[idx] = cn;
    h[idx] = sigm(go) * tanhf(cn);
}

// ---------------- final: lsm(hT)+lsm(x2) -> fin -> lsm over 16 ----------------
__device__ __forceinline__ float wredmax(float v){
#pragma unroll
    for (int o = 16; o; o >>= 1) v = fmaxf(v, __shfl_xor_sync(0xffffffffu, v, o));
    return v;
}
__device__ __forceinline__ float wredsum(float v){
#pragma unroll
    for (int o = 16; o; o >>= 1) v += __shfl_xor_sync(0xffffffffu, v, o);
    return v;
}

__global__ void final_kernel(const float* __restrict__ hT, const float* __restrict__ x2,
                             const float* __restrict__ finW, const float* __restrict__ finb,
                             float* __restrict__ out)
{
    int node = blockIdx.x * 8 + (threadIdx.x >> 5);
    if (node >= NNODE) return;
    int lane = threadIdx.x & 31;
    float4 hv = ((const float4*)(hT + node*HH))[lane];
    float4 xv = ((const float4*)(x2 + node*HH))[lane];
    // log_softmax of h row
    float mh = wredmax(fmaxf(fmaxf(hv.x, hv.y), fmaxf(hv.z, hv.w)));
    float sh = wredsum(expf(hv.x-mh) + expf(hv.y-mh) + expf(hv.z-mh) + expf(hv.w-mh));
    float lh = mh + logf(sh);
    // log_softmax of x row
    float mx = wredmax(fmaxf(fmaxf(xv.x, xv.y), fmaxf(xv.z, xv.w)));
    float sx = wredsum(expf(xv.x-mx) + expf(xv.y-mx) + expf(xv.z-mx) + expf(xv.w-mx));
    float lx = mx + logf(sx);
    float4 zx = make_float4(hv.x-lh + xv.x-lx, hv.y-lh + xv.y-lx,
                            hv.z-lh + xv.z-lx, hv.w-lh + xv.w-lx);
    float myo = 0.f;
#pragma unroll
    for (int cidx = 0; cidx < CC; cidx++){
        float4 w = ((const float4*)(finW + cidx*HH))[lane];
        float p = zx.x*w.x + zx.y*w.y + zx.z*w.z + zx.w*w.w;
        p = wredsum(p);
        if (lane == cidx) myo = p;
    }
    float v = (lane < CC) ? (myo + finb[lane]) : -1e30f;
    float m2 = wredmax(v);
    float e = (lane < CC) ? expf(v - m2) : 0.f;
    float s2 = wredsum(e);
    if (lane < CC) out[node*CC + lane] = v - m2 - logf(s2);
}

// ---------------- host ----------------
extern "C" void kernel_launch(void* const* d_in, const int* in_sizes, int n_in,
                              void* d_out, int out_size)
{
    const float* t_x   = (const float*)d_in[0];
    const int*   t_ei  = (const int*)  d_in[1];
    const float* s_x   = (const float*)d_in[2];
    const float* h0    = (const float*)d_in[3];
    const float* c0    = (const float*)d_in[4];
    const float* gcnW0 = (const float*)d_in[5];
    const float* gcnW1 = (const float*)d_in[6];
    const float* Wih   = (const float*)d_in[7];
    const float* Whh   = (const float*)d_in[8];
    const float* bih   = (const float*)d_in[9];
    const float* bhh   = (const float*)d_in[10];
    const float* nnW0  = (const float*)d_in[11];
    const float* nnb0  = (const float*)d_in[12];
    const float* nnW1  = (const float*)d_in[13];
    const float* nnb1  = (const float*)d_in[14];
    const float* nnW2  = (const float*)d_in[15];
    const float* nnb2  = (const float*)d_in[16];
    const float* finW  = (const float*)d_in[17];
    const float* finb  = (const float*)d_in[18];
    float* out = (float*)d_out;

    float *p_xw, *p_h1, *p_tf, *p_Wt, *p_y0, *p_y1, *p_x2, *p_gall, *p_ghh, *p_h, *p_c;
    cudaGetSymbolAddress((void**)&p_xw,   g_xw);
    cudaGetSymbolAddress((void**)&p_h1,   g_h1);
    cudaGetSymbolAddress((void**)&p_tf,   g_tf);
    cudaGetSymbolAddress((void**)&p_Wt,   g_Wt);
    cudaGetSymbolAddress((void**)&p_y0,   g_y0);
    cudaGetSymbolAddress((void**)&p_y1,   g_y1);
    cudaGetSymbolAddress((void**)&p_x2,   g_x2);
    cudaGetSymbolAddress((void**)&p_gall, g_gall);
    cudaGetSymbolAddress((void**)&p_ghh,  g_ghh);
    cudaGetSymbolAddress((void**)&p_h,    g_hst);
    cudaGetSymbolAddress((void**)&p_c,    g_cst);

    // ---- GCN adjacency prep (all 8 windows) ----
    zero_deg_kernel<<<(TT*NNODE + 255)/256, 256>>>();
    deg_kernel<<<(TT*EE + 255)/256, 256>>>(t_ei);
    dinv_fill_kernel<<<(TT*NNODE + 255)/256, 256>>>();
    scan_rowptr_kernel<<<TT, 1024>>>();
    scatter_kernel<<<(TT*EE + 255)/256, 256>>>(t_ei);
    sort_rows_kernel<<<dim3((NNODE + 7)/8, 1, TT), 256>>>();
    transpose_w_kernel<<<2*TT, 256>>>(gcnW0, gcnW1);

    // ---- GCN layer 0 (batched over windows) ----
    gemm_nt_kernel<<<dim3((NNODE + 63)/64, HH/64, TT), 256>>>(
        t_x, p_Wt, p_xw, NNODE, FIN, HH, nullptr, 0,
        (long)NNODE*FIN, (long)HH*HH, (long)NNODE*HH);
    gcn_gather_kernel<<<dim3((NNODE + 7)/8, 1, TT), 256>>>(p_xw, p_h1, 1);

    // ---- GCN layer 1 ----
    gemm_nt_kernel<<<dim3((NNODE + 63)/64, HH/64, TT), 256>>>(
        p_h1, p_Wt + TT*HH*HH, p_xw, NNODE, HH, HH, nullptr, 0,
        (long)NNODE*HH, (long)HH*HH, (long)NNODE*HH);
    gcn_gather_kernel<<<dim3((NNODE + 7)/8, 1, TT), 256>>>(p_xw, p_tf, 0);

    // ---- static MLP ----
    gemm_nt_kernel<<<dim3((NNODE + 63)/64, HIDNN/64, 1), 256>>>(
        s_x, nnW0, p_y0, NNODE, NNODE, HIDNN, nnb0, 1, 0, 0, 0);
    gemm_nt_kernel<<<dim3((NNODE + 63)/64, HID2/64, 1), 256>>>(
        p_y0, nnW1, p_y1, NNODE, HIDNN, HID2, nnb1, 0, 0, 0, 0);
    gemm_nt_kernel<<<dim3((NNODE + 63)/64, HH/64, 1), 256>>>(
        p_y1, nnW2, p_x2, NNODE, HID2, HH, nnb2, 0, 0, 0, 0);

    // ---- LSTM: all input projections in one GEMM ----
    gemm_nt_kernel<<<dim3((TT*NNODE + 63)/64, G4/64, 1), 256>>>(
        p_tf, Wih, p_gall, TT*NNODE, HH, G4, nullptr, 0, 0, 0, 0);

    cudaMemcpyAsync(p_h, h0, (size_t)NNODE*HH*sizeof(float), cudaMemcpyDeviceToDevice, 0);
    cudaMemcpyAsync(p_c, c0, (size_t)NNODE*HH*sizeof(float), cudaMemcpyDeviceToDevice, 0);

    for (int t = 0; t < TT; t++){
        gemm_nt_kernel<<<dim3((NNODE + 63)/64, G4/64, 1), 256>>>(
            p_h, Whh, p_ghh, NNODE, HH, G4, nullptr, 0, 0, 0, 0);
        lstm_gate_kernel<<<(NNODE*HH + 255)/256, 256>>>(
            p_gall + (long)t*NNODE*G4, p_ghh, bih, bhh, p_h, p_c);
    }

    // ---- final fused projection + log_softmax ----
    final_kernel<<<(NNODE + 7)/8, 256>>>(p_h, p_x2, finW, finb, out);
}

// round 4
// speedup vs baseline: 1.8419x; 1.8419x over previous
#include <cuda_runtime.h>
#include <cuda_bf16.h>
#include <math.h>
#include <stdint.h>

#define TT 8
#define NNODE 10000
#define FIN 128
#define HH 128
#define HIDNN 1024
#define HID2 256
#define CC 16
#define EE 320000
#define G4 (4*HH)

// ---------------- scratch (device globals; no runtime allocation) ----------------
__device__ float g_xw[TT*NNODE*HH];
__device__ float g_h1[TT*NNODE*HH];
__device__ float g_tf[TT*NNODE*HH];
__device__ int   g_deg[TT*NNODE];
__device__ int   g_fill[TT*NNODE];
__device__ float g_dinv[TT*NNODE];
__device__ int   g_rowptr[TT*(NNODE+1)];
__device__ int   g_colsrc[TT*EE];
__device__ float g_Wt[2*TT*HH*HH];
__device__ float g_y0[NNODE*HIDNN];
__device__ float g_y1[NNODE*HID2];
__device__ float g_x2[NNODE*HH];
__device__ float g_gall[TT*NNODE*G4];
__device__ float g_ghh[NNODE*G4];
__device__ float g_hst[NNODE*HH];
__device__ float g_cst[NNODE*HH];
// bf16 split operands for the big MLP0 GEMM
__device__ __nv_bfloat16 g_Ah[(size_t)NNODE*NNODE];
__device__ __nv_bfloat16 g_Al[(size_t)NNODE*NNODE];
__device__ __nv_bfloat16 g_Bh[(size_t)HIDNN*NNODE];
__device__ __nv_bfloat16 g_Bl[(size_t)HIDNN*NNODE];

// ================= helpers =================
__device__ __forceinline__ uint32_t smem_u32(const void* p){
    uint32_t a;
    asm("{ .reg .u64 t; cvta.to.shared.u64 t, %1; cvt.u32.u64 %0, t; }" : "=r"(a) : "l"(p));
    return a;
}
__device__ __forceinline__ void cp_async16(uint32_t dst, const void* src, int ssz){
    asm volatile("cp.async.cg.shared.global [%0], [%1], 16, %2;"
                 :: "r"(dst), "l"(src), "r"(ssz) : "memory");
}
__device__ __forceinline__ void cp_commit(){
    asm volatile("cp.async.commit_group;" ::: "memory");
}
__device__ __forceinline__ void cp_wait1(){
    asm volatile("cp.async.wait_group 1;" ::: "memory");
}
__device__ __forceinline__ void cp_wait0(){
    asm volatile("cp.async.wait_group 0;" ::: "memory");
}
__device__ __forceinline__ uint32_t lds32(uint32_t addr){
    uint32_t v;
    asm volatile("ld.shared.b32 %0, [%1];" : "=r"(v) : "r"(addr));
    return v;
}
__device__ __forceinline__ void mma16816(float* d, const uint32_t* a, const uint32_t* b){
    asm volatile("mma.sync.aligned.m16n8k16.row.col.f32.bf16.bf16.f32 "
                 "{%0,%1,%2,%3}, {%4,%5,%6,%7}, {%8,%9}, {%0,%1,%2,%3};"
                 : "+f"(d[0]), "+f"(d[1]), "+f"(d[2]), "+f"(d[3])
                 : "r"(a[0]), "r"(a[1]), "r"(a[2]), "r"(a[3]), "r"(b[0]), "r"(b[1]));
}

// ================= bf16 split kernel =================
__global__ void split_bf16_kernel(const float* __restrict__ x,
                                  __nv_bfloat16* __restrict__ hi,
                                  __nv_bfloat16* __restrict__ lo, long n)
{
    long i = ((long)blockIdx.x * blockDim.x + threadIdx.x) * 4;
    if (i >= n) return;
    float4 v = *(const float4*)(x + i);
    __nv_bfloat16 h0 = __float2bfloat16(v.x);
    __nv_bfloat16 h1 = __float2bfloat16(v.y);
    __nv_bfloat16 h2 = __float2bfloat16(v.z);
    __nv_bfloat16 h3 = __float2bfloat16(v.w);
    __nv_bfloat16 l0 = __float2bfloat16(v.x - __bfloat162float(h0));
    __nv_bfloat16 l1 = __float2bfloat16(v.y - __bfloat162float(h1));
    __nv_bfloat16 l2 = __float2bfloat16(v.z - __bfloat162float(h2));
    __nv_bfloat16 l3 = __float2bfloat16(v.w - __bfloat162float(h3));
    ushort4 hp = make_ushort4(*(unsigned short*)&h0, *(unsigned short*)&h1,
                              *(unsigned short*)&h2, *(unsigned short*)&h3);
    ushort4 lp = make_ushort4(*(unsigned short*)&l0, *(unsigned short*)&l1,
                              *(unsigned short*)&l2, *(unsigned short*)&l3);
    *(ushort4*)(hi + i) = hp;
    *(ushort4*)(lo + i) = lp;
}

// ================= HMMA split-bf16 GEMM: C = relu(A@B^T + bias) =================
// A: [10000, 10000] (Ah/Al), B: [1024, 10000] (Bh/Bl), C: [10000, 1024] f32
// CTA tile 128x128, warp tile 64x32, K-chunk 32, 2-stage cp.async pipeline.
#define KCH 32
#define ROWB 80                     // padded row stride in bytes (32 bf16 + 8 pad)
#define TILEB (128*ROWB)            // 10240 bytes per tile
#define BUFB  (4*TILEB)             // Ah,Al,Bh,Bl per stage = 40960
#define MMA_SMEM (2*BUFB)           // 81920
#define NCH 313                     // ceil(10000/32)

__global__ void __launch_bounds__(256, 2) mma_mlp0_kernel(
    const __nv_bfloat16* __restrict__ Ah, const __nv_bfloat16* __restrict__ Al,
    const __nv_bfloat16* __restrict__ Bh, const __nv_bfloat16* __restrict__ Bl,
    const float* __restrict__ bias, float* __restrict__ C)
{
    extern __shared__ char smem[];
    const uint32_t sb = smem_u32(smem);
    const int tid = threadIdx.x;
    const int wid = tid >> 5, lane = tid & 31;
    const int wm = wid >> 2, wn = wid & 3;          // warp grid 2x4
    const int m0 = blockIdx.y * 128;
    const int n0 = blockIdx.x * 128;

    const __nv_bfloat16* srcs[4] = {Ah, Al, Bh, Bl};

    // ---- loader lambda: fill stage buf with chunk c ----
    auto load_chunk = [&](int c, int buf){
        int k0 = c * KCH;
        uint32_t bbase = sb + buf * BUFB;
#pragma unroll
        for (int i = 0; i < 8; i++){
            int g = tid + i * 256;           // 0..2047
            int tile = g >> 9;               // 0..3
            int j = g & 511;
            int row = j >> 2;                // 0..127
            int gr = j & 3;                  // granule (8 bf16 = 16B)
            int kpos = k0 + gr * 8;
            int rem = NNODE - kpos;
            int grow = (tile < 2) ? (m0 + row) : (n0 + row);
            int ok = (tile < 2) ? (grow < NNODE) : 1;
            int ssz = ok ? (rem >= 8 ? 16 : (rem > 0 ? rem * 2 : 0)) : 0;
            const __nv_bfloat16* sp = srcs[tile];
            const void* p = ssz ? (const void*)(sp + (long)grow * NNODE + kpos)
                                : (const void*)sp;
            cp_async16(bbase + tile * TILEB + row * ROWB + gr * 16, p, ssz);
        }
        cp_commit();
    };

    float acc[4][4][4];
#pragma unroll
    for (int mi = 0; mi < 4; mi++)
#pragma unroll
        for (int ni = 0; ni < 4; ni++)
#pragma unroll
            for (int r = 0; r < 4; r++) acc[mi][ni][r] = 0.f;

    load_chunk(0, 0);

    const uint32_t arow = (uint32_t)(lane >> 2) * ROWB + (uint32_t)(lane & 3) * 4;

    for (int c = 0; c < NCH; c++){
        if (c + 1 < NCH){ load_chunk(c + 1, (c + 1) & 1); cp_wait1(); }
        else cp_wait0();
        __syncthreads();

        uint32_t bbase = sb + (c & 1) * BUFB;
        uint32_t aAh = bbase + 0 * TILEB + (uint32_t)(wm * 64) * ROWB + arow;
        uint32_t aAl = bbase + 1 * TILEB + (uint32_t)(wm * 64) * ROWB + arow;
        uint32_t aBh = bbase + 2 * TILEB + (uint32_t)(wn * 32) * ROWB + arow;
        uint32_t aBl = bbase + 3 * TILEB + (uint32_t)(wn * 32) * ROWB + arow;

#pragma unroll
        for (int pass = 0; pass < 3; pass++){
            uint32_t abase = (pass == 1) ? aAl : aAh;
            uint32_t bbase2 = (pass == 2) ? aBl : aBh;
#pragma unroll
            for (int k16 = 0; k16 < 2; k16++){
                uint32_t koff = (uint32_t)k16 * 32;
                uint32_t a[4][4], b[4][2];
#pragma unroll
                for (int mi = 0; mi < 4; mi++){
                    uint32_t p = abase + (uint32_t)(mi * 16) * ROWB + koff;
                    a[mi][0] = lds32(p);
                    a[mi][1] = lds32(p + 8 * ROWB);
                    a[mi][2] = lds32(p + 16);
                    a[mi][3] = lds32(p + 8 * ROWB + 16);
                }
#pragma unroll
                for (int ni = 0; ni < 4; ni++){
                    uint32_t p = bbase2 + (uint32_t)(ni * 8) * ROWB + koff;
                    b[ni][0] = lds32(p);
                    b[ni][1] = lds32(p + 16);
                }
#pragma unroll
                for (int mi = 0; mi < 4; mi++)
#pragma unroll
                    for (int ni = 0; ni < 4; ni++)
                        mma16816(acc[mi][ni], a[mi], b[ni]);
            }
        }
        __syncthreads();
    }

    // ---- epilogue: bias + relu, float2 stores ----
#pragma unroll
    for (int mi = 0; mi < 4; mi++){
        int row0 = m0 + wm * 64 + mi * 16 + (lane >> 2);
#pragma unroll
        for (int half = 0; half < 2; half++){
            int row = row0 + half * 8;
            if (row >= NNODE) continue;
            float* cp = C + (long)row * HIDNN;
#pragma unroll
            for (int ni = 0; ni < 4; ni++){
                int col = n0 + wn * 32 + ni * 8 + (lane & 3) * 2;
                float v0 = acc[mi][ni][half*2+0] + bias[col];
                float v1 = acc[mi][ni][half*2+1] + bias[col+1];
                float2 r = make_float2(fmaxf(v0, 0.f), fmaxf(v1, 0.f));
                *(float2*)(cp + col) = r;
            }
        }
    }
}

// ---------------- f32x2 packed-FMA helpers ----------------
__device__ __forceinline__ unsigned long long pk2(float lo, float hi){
    unsigned long long r;
    asm("mov.b64 %0, {%1, %2};" : "=l"(r) : "f"(lo), "f"(hi));
    return r;
}
__device__ __forceinline__ void ffma2(unsigned long long &d, unsigned long long a, unsigned long long b){
    asm("fma.rn.f32x2 %0, %1, %2, %0;" : "+l"(d) : "l"(a), "l"(b));
}
__device__ __forceinline__ float2 upk2(unsigned long long v){
    float2 r;
    asm("mov.b64 {%0, %1}, %2;" : "=f"(r.x), "=f"(r.y) : "l"(v));
    return r;
}

// ---------------- NT GEMM: C[M,Nc] = A[M,K] * B[Nc,K]^T (+bias, relu), batched over z ----------------
__global__ void gemm_nt_kernel(const float* __restrict__ A, const float* __restrict__ B,
                               float* __restrict__ C, int M, int K, int Nc,
                               const float* __restrict__ bias, int relu,
                               long sA, long sB, long sC)
{
    __shared__ float As[16][68];
    __shared__ float Bs[16][68];
    int z = blockIdx.z;
    A += (long)z * sA; B += (long)z * sB; C += (long)z * sC;
    int tid = threadIdx.x;
    int m0 = blockIdx.x * 64, n0 = blockIdx.y * 64;
    int lr = tid >> 2;
    int lk = (tid & 3) << 2;
    const float* Ap = A + (long)(m0 + lr) * K + lk;
    const float* Bp = B + (long)(n0 + lr) * K + lk;
    bool aval = (m0 + lr) < M;
    int ty = tid >> 4, tx = tid & 15;
    unsigned long long acc[4][2];
#pragma unroll
    for (int i = 0; i < 4; i++){ acc[i][0] = 0ULL; acc[i][1] = 0ULL; }

    for (int k0 = 0; k0 < K; k0 += 16){
        float4 av = aval ? *(const float4*)Ap : make_float4(0.f,0.f,0.f,0.f);
        float4 bv = *(const float4*)Bp;
        Ap += 16; Bp += 16;
        __syncthreads();
        As[lk+0][lr]=av.x; As[lk+1][lr]=av.y; As[lk+2][lr]=av.z; As[lk+3][lr]=av.w;
        Bs[lk+0][lr]=bv.x; Bs[lk+1][lr]=bv.y; Bs[lk+2][lr]=bv.z; Bs[lk+3][lr]=bv.w;
        __syncthreads();
#pragma unroll
        for (int kk = 0; kk < 16; kk++){
            float4 a4 = *(const float4*)&As[kk][ty*4];
            float4 b4 = *(const float4*)&Bs[kk][tx*4];
            unsigned long long b01 = pk2(b4.x, b4.y), b23 = pk2(b4.z, b4.w);
            unsigned long long a0 = pk2(a4.x, a4.x);
            unsigned long long a1 = pk2(a4.y, a4.y);
            unsigned long long a2 = pk2(a4.z, a4.z);
            unsigned long long a3 = pk2(a4.w, a4.w);
            ffma2(acc[0][0], a0, b01); ffma2(acc[0][1], a0, b23);
            ffma2(acc[1][0], a1, b01); ffma2(acc[1][1], a1, b23);
            ffma2(acc[2][0], a2, b01); ffma2(acc[2][1], a2, b23);
            ffma2(acc[3][0], a3, b01); ffma2(acc[3][1], a3, b23);
        }
    }
#pragma unroll
    for (int i = 0; i < 4; i++){
        int row = m0 + ty*4 + i;
        if (row >= M) continue;
        float2 v0 = upk2(acc[i][0]), v1 = upk2(acc[i][1]);
        int col = n0 + tx*4;
        float4 r = make_float4(v0.x, v0.y, v1.x, v1.y);
        if (bias){ r.x += bias[col]; r.y += bias[col+1]; r.z += bias[col+2]; r.w += bias[col+3]; }
        if (relu){ r.x=fmaxf(r.x,0.f); r.y=fmaxf(r.y,0.f); r.z=fmaxf(r.z,0.f); r.w=fmaxf(r.w,0.f); }
        *(float4*)(C + (long)row * Nc + col) = r;
    }
}

// ---------------- GCN prep kernels ----------------
__global__ void zero_deg_kernel(){
    int i = blockIdx.x * blockDim.x + threadIdx.x;
    if (i < TT*NNODE) g_deg[i] = 0;
}

__global__ void deg_kernel(const int* __restrict__ ei){
    int idx = blockIdx.x * blockDim.x + threadIdx.x;
    if (idx >= TT*EE) return;
    int t = idx / EE, e = idx - t*EE;
    int d = ei[t*2*EE + EE + e];
    atomicAdd(&g_deg[t*NNODE + d], 1);
}

__global__ void dinv_fill_kernel(){
    int i = blockIdx.x * blockDim.x + threadIdx.x;
    if (i >= TT*NNODE) return;
    g_dinv[i] = rsqrtf((float)(g_deg[i] + 1));
    g_fill[i] = 0;
}

__global__ void scan_rowptr_kernel(){
    int t = blockIdx.x;
    const int* d = g_deg + t*NNODE;
    int* rp = g_rowptr + t*(NNODE+1);
    __shared__ int s[1024];
    int carry = 0;
    if (threadIdx.x == 0) rp[0] = 0;
    for (int base = 0; base < NNODE; base += 1024){
        int i = base + threadIdx.x;
        int v = (i < NNODE) ? d[i] : 0;
        s[threadIdx.x] = v;
        __syncthreads();
        for (int off = 1; off < 1024; off <<= 1){
            int add = (threadIdx.x >= off) ? s[threadIdx.x - off] : 0;
            __syncthreads();
            s[threadIdx.x] += add;
            __syncthreads();
        }
        if (i < NNODE) rp[i+1] = carry + s[threadIdx.x];
        carry += s[1023];
        __syncthreads();
    }
}

__global__ void scatter_kernel(const int* __restrict__ ei){
    int idx = blockIdx.x * blockDim.x + threadIdx.x;
    if (idx >= TT*EE) return;
    int t = idx / EE, e = idx - t*EE;
    int s = ei[t*2*EE + e];
    int d = ei[t*2*EE + EE + e];
    int pos = g_rowptr[t*(NNODE+1) + d] + atomicAdd(&g_fill[t*NNODE + d], 1);
    g_colsrc[t*EE + pos] = s;
}

__global__ void sort_rows_kernel(){
    int t = blockIdx.z;
    int node = blockIdx.x * 8 + (threadIdx.x >> 5);
    int lane = threadIdx.x & 31;
    __shared__ int sh[8][256];
    if (node >= NNODE) return;
    int* buf = sh[threadIdx.x >> 5];
    int* cs = g_colsrc + t*EE;
    int s0 = g_rowptr[t*(NNODE+1) + node];
    int s1 = g_rowptr[t*(NNODE+1) + node + 1];
    int len = s1 - s0;
    if (len <= 1 || len > 256) return;
    for (int i = lane; i < len; i += 32) buf[i] = cs[s0 + i];
    __syncwarp();
    for (int p = 0; p < len; p++){
        int start = p & 1;
        for (int i = start + 2*lane; i < len - 1; i += 64){
            int a = buf[i], b = buf[i+1];
            if (a > b){ buf[i] = b; buf[i+1] = a; }
        }
        __syncwarp();
    }
    for (int i = lane; i < len; i += 32) cs[s0 + i] = buf[i];
}

__global__ void transpose_w_kernel(const float* __restrict__ W0, const float* __restrict__ W1){
    int m = blockIdx.x;
    const float* src = (m < TT) ? (W0 + m*HH*HH) : (W1 + (m-TT)*HH*HH);
    float* dst = g_Wt + m*HH*HH;
    for (int i = threadIdx.x; i < HH*HH; i += blockDim.x){
        int k = i >> 7, j = i & 127;
        dst[j*HH + k] = src[i];
    }
}

__global__ void gcn_gather_kernel(const float* __restrict__ xw, float* __restrict__ out, int relu){
    int t = blockIdx.z;
    int node = blockIdx.x * 8 + (threadIdx.x >> 5);
    if (node >= NNODE) return;
    int lane = threadIdx.x & 31;
    const float* xwT = xw + (long)t*NNODE*HH;
    float* outT = out + (long)t*NNODE*HH;
    const int* rp = g_rowptr + t*(NNODE+1);
    const int* cs = g_colsrc + t*EE;
    const float* dv = g_dinv + t*NNODE;
    float dn = dv[node];
    float4 acc = ((const float4*)(xwT + node*HH))[lane];
    float w0 = dn * dn;
    acc.x *= w0; acc.y *= w0; acc.z *= w0; acc.w *= w0;
    int e0 = rp[node], e1 = rp[node+1];
    for (int e = e0; e < e1; e++){
        int s = cs[e];
        float w = dv[s] * dn;
        float4 v = ((const float4*)(xwT + s*HH))[lane];
        acc.x += v.x * w; acc.y += v.y * w; acc.z += v.z * w; acc.w += v.w * w;
    }
    if (relu){
        acc.x = fmaxf(acc.x, 0.f); acc.y = fmaxf(acc.y, 0.f);
        acc.z = fmaxf(acc.z, 0.f); acc.w = fmaxf(acc.w, 0.f);
    }
    ((float4*)(outT + node*HH))[lane] = acc;
}

// ---------------- LSTM gate kernel ----------------
__device__ __forceinline__ float sigm(float x){ return 1.f / (1.f + expf(-x)); }

__global__ void lstm_gate_kernel(const float* __restrict__ gxt, const float* __restrict__ ghh,
                                 const float* __restrict__ bih, const float* __restrict__ bhh,
                                 float* __restrict__ h, float* __restrict__ c)
{
    int idx = blockIdx.x * blockDim.x + threadIdx.x;
    if (idx >= NNODE*HH) return;
    int n = idx >> 7, k = idx & 127;
    const float* gx = gxt + n*G4;
    const float* gh = ghh + n*G4;
    float gi = gx[k]       + gh[k]       + bih[k]       + bhh[k];
    float gf = gx[HH+k]    + gh[HH+k]    + bih[HH+k]    + bhh[HH+k];
    float gg = gx[2*HH+k]  + gh[2*HH+k]  + bih[2*HH+k]  + bhh[2*HH+k];
    float go = gx[3*HH+k]  + gh[3*HH+k]  + bih[3*HH+k]  + bhh[3*HH+k];
    float cn = sigm(gf) * c[idx] + sigm(gi) * tanhf(gg);
    c[idx] = cn;
    h[idx] = sigm(go) * tanhf(cn);
}

// ---------------- final fused kernel ----------------
__device__ __forceinline__ float wredmax(float v){
#pragma unroll
    for (int o = 16; o; o >>= 1) v = fmaxf(v, __shfl_xor_sync(0xffffffffu, v, o));
    return v;
}
__device__ __forceinline__ float wredsum(float v){
#pragma unroll
    for (int o = 16; o; o >>= 1) v += __shfl_xor_sync(0xffffffffu, v, o);
    return v;
}

__global__ void final_kernel(const float* __restrict__ hT, const float* __restrict__ x2,
                             const float* __restrict__ finW, const float* __restrict__ finb,
                             float* __restrict__ out)
{
    int node = blockIdx.x * 8 + (threadIdx.x >> 5);
    if (node >= NNODE) return;
    int lane = threadIdx.x & 31;
    float4 hv = ((const float4*)(hT + node*HH))[lane];
    float4 xv = ((const float4*)(x2 + node*HH))[lane];
    float mh = wredmax(fmaxf(fmaxf(hv.x, hv.y), fmaxf(hv.z, hv.w)));
    float sh = wredsum(expf(hv.x-mh) + expf(hv.y-mh) + expf(hv.z-mh) + expf(hv.w-mh));
    float lh = mh + logf(sh);
    float mx = wredmax(fmaxf(fmaxf(xv.x, xv.y), fmaxf(xv.z, xv.w)));
    float sx = wredsum(expf(xv.x-mx) + expf(xv.y-mx) + expf(xv.z-mx) + expf(xv.w-mx));
    float lx = mx + logf(sx);
    float4 zx = make_float4(hv.x-lh + xv.x-lx, hv.y-lh + xv.y-lx,
                            hv.z-lh + xv.z-lx, hv.w-lh + xv.w-lx);
    float myo = 0.f;
#pragma unroll
    for (int cidx = 0; cidx < CC; cidx++){
        float4 w = ((const float4*)(finW + cidx*HH))[lane];
        float p = zx.x*w.x + zx.y*w.y + zx.z*w.z + zx.w*w.w;
        p = wredsum(p);
        if (lane == cidx) myo = p;
    }
    float v = (lane < CC) ? (myo + finb[lane]) : -1e30f;
    float m2 = wredmax(v);
    float e = (lane < CC) ? expf(v - m2) : 0.f;
    float s2 = wredsum(e);
    if (lane < CC) out[node*CC + lane] = v - m2 - logf(s2);
}

// ---------------- host ----------------
extern "C" void kernel_launch(void* const* d_in, const int* in_sizes, int n_in,
                              void* d_out, int out_size)
{
    const float* t_x   = (const float*)d_in[0];
    const int*   t_ei  = (const int*)  d_in[1];
    const float* s_x   = (const float*)d_in[2];
    const float* h0    = (const float*)d_in[3];
    const float* c0    = (const float*)d_in[4];
    const float* gcnW0 = (const float*)d_in[5];
    const float* gcnW1 = (const float*)d_in[6];
    const float* Wih   = (const float*)d_in[7];
    const float* Whh   = (const float*)d_in[8];
    const float* bih   = (const float*)d_in[9];
    const float* bhh   = (const float*)d_in[10];
    const float* nnW0  = (const float*)d_in[11];
    const float* nnb0  = (const float*)d_in[12];
    const float* nnW1  = (const float*)d_in[13];
    const float* nnb1  = (const float*)d_in[14];
    const float* nnW2  = (const float*)d_in[15];
    const float* nnb2  = (const float*)d_in[16];
    const float* finW  = (const float*)d_in[17];
    const float* finb  = (const float*)d_in[18];
    float* out = (float*)d_out;

    float *p_xw, *p_h1, *p_tf, *p_Wt, *p_y0, *p_y1, *p_x2, *p_gall, *p_ghh, *p_h, *p_c;
    __nv_bfloat16 *p_Ah, *p_Al, *p_Bh, *p_Bl;
    cudaGetSymbolAddress((void**)&p_xw,   g_xw);
    cudaGetSymbolAddress((void**)&p_h1,   g_h1);
    cudaGetSymbolAddress((void**)&p_tf,   g_tf);
    cudaGetSymbolAddress((void**)&p_Wt,   g_Wt);
    cudaGetSymbolAddress((void**)&p_y0,   g_y0);
    cudaGetSymbolAddress((void**)&p_y1,   g_y1);
    cudaGetSymbolAddress((void**)&p_x2,   g_x2);
    cudaGetSymbolAddress((void**)&p_gall, g_gall);
    cudaGetSymbolAddress((void**)&p_ghh,  g_ghh);
    cudaGetSymbolAddress((void**)&p_h,    g_hst);
    cudaGetSymbolAddress((void**)&p_c,    g_cst);
    cudaGetSymbolAddress((void**)&p_Ah,   g_Ah);
    cudaGetSymbolAddress((void**)&p_Al,   g_Al);
    cudaGetSymbolAddress((void**)&p_Bh,   g_Bh);
    cudaGetSymbolAddress((void**)&p_Bl,   g_Bl);

    // ---- split inputs of the big GEMM into bf16 hi/lo ----
    {
        long nA = (long)NNODE * NNODE;
        long nB = (long)HIDNN * NNODE;
        split_bf16_kernel<<<(unsigned)((nA/4 + 255)/256), 256>>>(s_x,  p_Ah, p_Al, nA);
        split_bf16_kernel<<<(unsigned)((nB/4 + 255)/256), 256>>>(nnW0, p_Bh, p_Bl, nB);
    }

    // ---- GCN adjacency prep ----
    zero_deg_kernel<<<(TT*NNODE + 255)/256, 256>>>();
    deg_kernel<<<(TT*EE + 255)/256, 256>>>(t_ei);
    dinv_fill_kernel<<<(TT*NNODE + 255)/256, 256>>>();
    scan_rowptr_kernel<<<TT, 1024>>>();
    scatter_kernel<<<(TT*EE + 255)/256, 256>>>(t_ei);
    sort_rows_kernel<<<dim3((NNODE + 7)/8, 1, TT), 256>>>();
    transpose_w_kernel<<<2*TT, 256>>>(gcnW0, gcnW1);

    // ---- GCN layer 0 ----
    gemm_nt_kernel<<<dim3((NNODE + 63)/64, HH/64, TT), 256>>>(
        t_x, p_Wt, p_xw, NNODE, FIN, HH, nullptr, 0,
        (long)NNODE*FIN, (long)HH*HH, (long)NNODE*HH);
    gcn_gather_kernel<<<dim3((NNODE + 7)/8, 1, TT), 256>>>(p_xw, p_h1, 1);

    // ---- GCN layer 1 ----
    gemm_nt_kernel<<<dim3((NNODE + 63)/64, HH/64, TT), 256>>>(
        p_h1, p_Wt + TT*HH*HH, p_xw, NNODE, HH, HH, nullptr, 0,
        (long)NNODE*HH, (long)HH*HH, (long)NNODE*HH);
    gcn_gather_kernel<<<dim3((NNODE + 7)/8, 1, TT), 256>>>(p_xw, p_tf, 0);

    // ---- static MLP layer 0 on HMMA tensor cores (split-bf16 3-pass) ----
    cudaFuncSetAttribute(mma_mlp0_kernel,
                         cudaFuncAttributeMaxDynamicSharedMemorySize, MMA_SMEM);
    mma_mlp0_kernel<<<dim3(HIDNN/128, (NNODE + 127)/128), 256, MMA_SMEM>>>(
        p_Ah, p_Al, p_Bh, p_Bl, nnb0, p_y0);

    // ---- static MLP layers 1,2 ----
    gemm_nt_kernel<<<dim3((NNODE + 63)/64, HID2/64, 1), 256>>>(
        p_y0, nnW1, p_y1, NNODE, HIDNN, HID2, nnb1, 0, 0, 0, 0);
    gemm_nt_kernel<<<dim3((NNODE + 63)/64, HH/64, 1), 256>>>(
        p_y1, nnW2, p_x2, NNODE, HID2, HH, nnb2, 0, 0, 0, 0);

    // ---- LSTM input projections ----
    gemm_nt_kernel<<<dim3((TT*NNODE + 63)/64, G4/64, 1), 256>>>(
        p_tf, Wih, p_gall, TT*NNODE, HH, G4, nullptr, 0, 0, 0, 0);

    cudaMemcpyAsync(p_h, h0, (size_t)NNODE*HH*sizeof(float), cudaMemcpyDeviceToDevice, 0);
    cudaMemcpyAsync(p_c, c0, (size_t)NNODE*HH*sizeof(float), cudaMemcpyDeviceToDevice, 0);

    for (int t = 0; t < TT; t++){
        gemm_nt_kernel<<<dim3((NNODE + 63)/64, G4/64, 1), 256>>>(
            p_h, Whh, p_ghh, NNODE, HH, G4, nullptr, 0, 0, 0, 0);
        lstm_gate_kernel<<<(NNODE*HH + 255)/256, 256>>>(
            p_gall + (long)t*NNODE*G4, p_ghh, bih, bhh, p_h, p_c);
    }

    final_kernel<<<(NNODE + 7)/8, 256>>>(p_h, p_x2, finW, finb, out);
}